// round 6
// baseline (speedup 1.0000x reference)
#include <cuda_runtime.h>
#include <math.h>

typedef unsigned long long u64;

#define T_    2048
#define NB_   64
#define NU_   8
#define NH_   256
#define H2_   128
#define NY_   8
#define S_    32
#define L_    64           // T_/S_
#define NSQ_  6            // log2(L_)
#define NBP_  32           // NB_/2 (batch pairs)
#define CH_   16           // chunk of timesteps
#define NCH_  4            // L_/CH_
#define XROW_ 258          // padded Xs row (in u64) to break bank conflicts

// scratch (device globals; no allocation allowed)
__device__ u64 g_final[S_][NBP_][H2_][2];
__device__ u64 g_init [S_][NBP_][H2_][2];

// ---- packed f32x2 helpers (Blackwell FFMA2 path) ----
static __device__ __forceinline__ u64 pk2(float lo, float hi) {
    u64 r; asm("mov.b64 %0, {%1,%2};" : "=l"(r) : "f"(lo), "f"(hi)); return r;
}
static __device__ __forceinline__ void upk2(u64 v, float& lo, float& hi) {
    asm("mov.b64 {%0,%1}, %2;" : "=f"(lo), "=f"(hi) : "l"(v));
}
static __device__ __forceinline__ u64 ffma2(u64 a, u64 b, u64 c) {
    u64 d; asm("fma.rn.f32x2 %0,%1,%2,%3;" : "=l"(d) : "l"(a), "l"(b), "l"(c)); return d;
}
static __device__ __forceinline__ u64 fmul2(u64 a, u64 b) {
    u64 d; asm("mul.rn.f32x2 %0,%1,%2;" : "=l"(d) : "l"(a), "l"(b)); return d;
}
static __device__ __forceinline__ u64 fadd2(u64 a, u64 b) {
    u64 d; asm("add.rn.f32x2 %0,%1,%2;" : "=l"(d) : "l"(a), "l"(b)); return d;
}

// lambda in double (robust to fast-math; amplification through scan ~L*eps)
static __device__ __forceinline__ void lam_of(const float* lr, const float* li, int h,
                                              float& re, float& im) {
    double r  = exp(-fabs((double)lr[h]));
    double th = 1.5707963267948966 * (double)li[h];
    re = (float)(r * cos(th));
    im = (float)(r * sin(th));
}

// =====================================================================
// Kernel 1: per-segment local scan (zero init) -> g_final
// grid (NBP_, S_), 128 threads (one complex pair each, packed over 2 batches)
// =====================================================================
__global__ void __launch_bounds__(128, 7) k_seg(
    const float* __restrict__ U, const float* __restrict__ lr, const float* __restrict__ li,
    const float* __restrict__ B, const float* __restrict__ mB)
{
    const int h  = threadIdx.x;
    const int bp = blockIdx.x;
    const int s  = blockIdx.y;
    const int b0 = bp << 1;

    float e1 = (float)exp((double)mB[h]);
    float e2 = (float)exp((double)mB[h + H2_]);
    u64 Bp1[NU_], Bp2[NU_];
#pragma unroll
    for (int u = 0; u < NU_; ++u) {
        float w1 = B[h * NU_ + u] * e1;
        float w2 = B[(h + H2_) * NU_ + u] * e2;
        Bp1[u] = pk2(w1, w1);
        Bp2[u] = pk2(w2, w2);
    }
    float re, im; lam_of(lr, li, h, re, im);
    u64 re2 = pk2(re, re), im2 = pk2(im, im), ni2 = pk2(-im, -im);

    u64 x1 = 0ull, x2 = 0ull;

    __shared__ __align__(16) u64 Us[CH_][NU_];
    const float* Ub = U + ((size_t)s * L_ * NB_ + b0) * NU_;

    for (int c = 0; c < NCH_; ++c) {
        __syncthreads();
        {   // stage CH_ steps of U, packed over the batch pair
            int t = h >> 3, u = h & 7;
            const float* p = Ub + (size_t)(c * CH_ + t) * (NB_ * NU_) + u;
            Us[t][u] = pk2(p[0], p[NU_]);
        }
        __syncthreads();
#pragma unroll
        for (int t = 0; t < CH_; ++t) {
            const ulonglong2* up = (const ulonglong2*)(&Us[t][0]);
            ulonglong2 ua = up[0], ub = up[1], uc = up[2], ud = up[3];
            u64 uu[8] = { ua.x, ua.y, ub.x, ub.y, uc.x, uc.y, ud.x, ud.y };
            u64 bu1 = fmul2(Bp1[0], uu[0]);
            u64 bu2 = fmul2(Bp2[0], uu[0]);
#pragma unroll
            for (int u = 1; u < NU_; ++u) {
                bu1 = ffma2(Bp1[u], uu[u], bu1);
                bu2 = ffma2(Bp2[u], uu[u], bu2);
            }
            u64 nx1 = ffma2(re2, x1, ffma2(ni2, x2, bu1));
            u64 nx2 = ffma2(re2, x2, ffma2(im2, x1, bu2));
            x1 = nx1; x2 = nx2;
        }
    }
    g_final[s][bp][h][0] = x1;
    g_final[s][bp][h][1] = x2;
}

// =====================================================================
// Kernel 2: sequential combine across segments -> g_init
// grid (NBP_), 128 threads
// =====================================================================
__global__ void __launch_bounds__(128, 1) k_comb(
    const float* __restrict__ y0, const float* __restrict__ lr, const float* __restrict__ li,
    const float* __restrict__ Wyx, const float* __restrict__ byx)
{
    const int h  = threadIdx.x;
    const int bp = blockIdx.x;
    const int b0 = bp << 1;

    float re, im; lam_of(lr, li, h, re, im);
    // lambda^L by repeated squaring in double (L_ = 2^NSQ_)
    double pr = (double)re, pi = (double)im;
#pragma unroll
    for (int i = 0; i < NSQ_; ++i) {
        double nr = pr * pr - pi * pi;
        double ni = 2.0 * pr * pi;
        pr = nr; pi = ni;
    }
    float prf = (float)pr, pif = (float)pi;
    u64 pr2 = pk2(prf, prf), pi2 = pk2(pif, pif), npi2 = pk2(-pif, -pif);

    // x0 = y0 @ Wy2x^T + by2x, packed over batch pair
    float bb1 = byx[h], bb2 = byx[h + H2_];
    u64 z1 = pk2(bb1, bb1), z2 = pk2(bb2, bb2);
#pragma unroll
    for (int y = 0; y < NY_; ++y) {
        u64 yv = pk2(y0[b0 * NY_ + y], y0[(b0 + 1) * NY_ + y]);
        float w1 = Wyx[h * NY_ + y];
        float w2 = Wyx[(h + H2_) * NY_ + y];
        z1 = ffma2(pk2(w1, w1), yv, z1);
        z2 = ffma2(pk2(w2, w2), yv, z2);
    }
#pragma unroll
    for (int s = 0; s < S_; ++s) {
        g_init[s][bp][h][0] = z1;
        g_init[s][bp][h][1] = z2;
        u64 f1 = g_final[s][bp][h][0];
        u64 f2 = g_final[s][bp][h][1];
        u64 n1 = ffma2(pr2, z1, ffma2(npi2, z2, f1));
        u64 n2 = ffma2(pr2, z2, ffma2(pi2,  z1, f2));
        z1 = n1; z2 = n2;
    }
}

// =====================================================================
// Kernel 3: re-scan with correct init + fused Y projection
// grid (NBP_, S_), 128 threads, dynamic shared
// shared layout (u64): Xs[CH_][XROW_] | Wk[NH_][NY_] | Us[CH_][NU_] | Rd[4][CH_][NY_]
// =====================================================================
#define SM3_U64 (CH_ * XROW_ + NH_ * NY_ + CH_ * NU_ + 4 * CH_ * NY_)
#define SM3_BYTES (SM3_U64 * 8)

__global__ void __launch_bounds__(128, 4) k_main(
    const float* __restrict__ U, const float* __restrict__ lr, const float* __restrict__ li,
    const float* __restrict__ B, const float* __restrict__ mB,
    const float* __restrict__ Wxy, const float* __restrict__ bxy,
    float* __restrict__ Y)
{
    extern __shared__ __align__(16) u64 sm[];
    u64* Xs = sm;                        // [CH_][XROW_], col k: 2h->x1, 2h+1->x2
    u64* Wk = sm + CH_ * XROW_;          // [NH_][NY_], packed splats, interleaved cols
    u64* Us = Wk + NH_ * NY_;            // [CH_][NU_]
    u64* Rd = Us + CH_ * NU_;            // [4][CH_][NY_] (after in-warp kg-pair reduce)

    const int tid = threadIdx.x;
    const int h   = tid;
    const int bp  = blockIdx.x;
    const int s   = blockIdx.y;
    const int b0  = bp << 1;

    // prepack W (interleave column order to match Xs layout)
#pragma unroll
    for (int i = 0; i < 16; ++i) {
        int idx = tid * 16 + i;          // 0..2047
        int k = idx >> 3, y = idx & 7;
        int hh = k >> 1;
        int col = (k & 1) ? (hh + H2_) : hh;
        float w = Wxy[y * NH_ + col];
        Wk[k * NY_ + y] = pk2(w, w);
    }

    float e1 = (float)exp((double)mB[h]);
    float e2 = (float)exp((double)mB[h + H2_]);
    u64 Bp1[NU_], Bp2[NU_];
#pragma unroll
    for (int u = 0; u < NU_; ++u) {
        float w1 = B[h * NU_ + u] * e1;
        float w2 = B[(h + H2_) * NU_ + u] * e2;
        Bp1[u] = pk2(w1, w1);
        Bp2[u] = pk2(w2, w2);
    }
    float re, im; lam_of(lr, li, h, re, im);
    u64 re2 = pk2(re, re), im2 = pk2(im, im), ni2 = pk2(-im, -im);

    u64 x1 = g_init[s][bp][h][0];
    u64 x2 = g_init[s][bp][h][1];

    // output-role constants
    const int ot = tid >> 3;             // t within chunk for the final reduce
    const int oy = tid & 7;
    float bb = bxy[oy];
    const u64 biasp = pk2(bb, bb);

    // phase-B role
    const int pt = tid & 15;             // t within chunk
    const int kg = tid >> 4;             // 0..7 -> k range [32kg, 32kg+32)
    const int kbase = kg * 32;
    const bool kg_even = ((tid >> 4) & 1) == 0;
    const int g = kg >> 1;               // 0..3 after in-warp pair reduce

    const float* Ub = U + ((size_t)s * L_ * NB_ + b0) * NU_;

    for (int c = 0; c < NCH_; ++c) {
        __syncthreads();
        {   // stage U chunk
            int t = tid >> 3, u = tid & 7;
            const float* p = Ub + (size_t)(c * CH_ + t) * (NB_ * NU_) + u;
            Us[t * NU_ + u] = pk2(p[0], p[NU_]);
        }
        __syncthreads();

        // ---- phase A: scan CH_ steps, stash states in shared ----
#pragma unroll
        for (int t = 0; t < CH_; ++t) {
            const ulonglong2* up = (const ulonglong2*)(Us + t * NU_);
            ulonglong2 ua = up[0], ub = up[1], uc = up[2], ud = up[3];
            u64 uu[8] = { ua.x, ua.y, ub.x, ub.y, uc.x, uc.y, ud.x, ud.y };
            u64 bu1 = fmul2(Bp1[0], uu[0]);
            u64 bu2 = fmul2(Bp2[0], uu[0]);
#pragma unroll
            for (int u = 1; u < NU_; ++u) {
                bu1 = ffma2(Bp1[u], uu[u], bu1);
                bu2 = ffma2(Bp2[u], uu[u], bu2);
            }
            u64 nx1 = ffma2(re2, x1, ffma2(ni2, x2, bu1));
            u64 nx2 = ffma2(re2, x2, ffma2(im2, x1, bu2));
            x1 = nx1; x2 = nx2;
            *((ulonglong2*)(Xs + (size_t)t * XROW_ + 2 * h)) = make_ulonglong2(x1, x2);
        }
        __syncthreads();

        // ---- phase B: Y partial GEMM, thread = (pt, kg), all 8 y ----
        u64 acc[NY_];
#pragma unroll
        for (int y = 0; y < NY_; ++y) acc[y] = 0ull;
        const u64* xrow = Xs + (size_t)pt * XROW_ + kbase;
#pragma unroll
        for (int k4 = 0; k4 < 32; k4 += 4) {
            ulonglong2 xa = *((const ulonglong2*)(xrow + k4));
            ulonglong2 xb = *((const ulonglong2*)(xrow + k4 + 2));
            u64 xv[4] = { xa.x, xa.y, xb.x, xb.y };
#pragma unroll
            for (int j = 0; j < 4; ++j) {
                const ulonglong2* wr = (const ulonglong2*)(Wk + (size_t)(kbase + k4 + j) * NY_);
                ulonglong2 w0 = wr[0], w1 = wr[1], w2 = wr[2], w3 = wr[3];
                acc[0] = ffma2(w0.x, xv[j], acc[0]);
                acc[1] = ffma2(w0.y, xv[j], acc[1]);
                acc[2] = ffma2(w1.x, xv[j], acc[2]);
                acc[3] = ffma2(w1.y, xv[j], acc[3]);
                acc[4] = ffma2(w2.x, xv[j], acc[4]);
                acc[5] = ffma2(w2.y, xv[j], acc[5]);
                acc[6] = ffma2(w3.x, xv[j], acc[6]);
                acc[7] = ffma2(w3.y, xv[j], acc[7]);
            }
        }

        // in-warp pre-reduce: lane tid^16 has same pt, kg^1
#pragma unroll
        for (int y = 0; y < NY_; ++y) {
            u64 o = __shfl_xor_sync(0xFFFFFFFFu, acc[y], 16);
            acc[y] = fadd2(acc[y], o);
        }
        if (kg_even) {
#pragma unroll
            for (int y = 0; y < NY_; y += 2) {
                *((ulonglong2*)(Rd + (size_t)(g * CH_ + pt) * NY_ + y)) =
                    make_ulonglong2(acc[y], acc[y + 1]);
            }
        }
        __syncthreads();

        // ---- final reduce over 4 groups + bias + store ----
        {
            u64 sum = Rd[(size_t)(0 * CH_ + ot) * NY_ + oy];
#pragma unroll
            for (int gg = 1; gg < 4; ++gg)
                sum = fadd2(sum, Rd[(size_t)(gg * CH_ + ot) * NY_ + oy]);
            sum = fadd2(sum, biasp);
            float f0, f1; upk2(sum, f0, f1);
            int tg = s * L_ + c * CH_ + ot;
            float* yp = Y + ((size_t)tg * NB_ + b0) * NY_ + oy;
            yp[0]   = f0;
            yp[NY_] = f1;
        }
    }
}

// =====================================================================
extern "C" void kernel_launch(void* const* d_in, const int* in_sizes, int n_in,
                              void* d_out, int out_size)
{
    const float* y0  = (const float*)d_in[0];
    const float* U   = (const float*)d_in[1];
    const float* lr  = (const float*)d_in[2];
    const float* li  = (const float*)d_in[3];
    const float* B   = (const float*)d_in[4];
    const float* mB  = (const float*)d_in[5];
    const float* Wyx = (const float*)d_in[6];
    const float* byx = (const float*)d_in[7];
    const float* Wxy = (const float*)d_in[8];
    const float* bxy = (const float*)d_in[9];
    float* Y = (float*)d_out;

    cudaFuncSetAttribute(k_main, cudaFuncAttributeMaxDynamicSharedMemorySize, SM3_BYTES);

    dim3 grid(NBP_, S_);
    k_seg <<<grid, 128>>>(U, lr, li, B, mB);
    k_comb<<<NBP_, 128>>>(y0, lr, li, Wyx, byx);
    k_main<<<grid, 128, SM3_BYTES>>>(U, lr, li, B, mB, Wxy, bxy, Y);
}

// round 7
// speedup vs baseline: 1.3100x; 1.3100x over previous
#include <cuda_runtime.h>
#include <math.h>

typedef unsigned long long u64;

#define T_    2048
#define NB_   64
#define NU_   8
#define NH_   256
#define H2_   128
#define NY_   8
#define S_    32
#define L_    64           // T_/S_
#define NSQ_  6            // log2(L_)
#define NBP_  32           // NB_/2 (batch pairs)
#define CH_   16           // chunk of timesteps
#define NCH_  4            // L_/CH_
#define XROW_ 258          // padded Xs row (in u64) to break bank conflicts

// scratch (device globals; no allocation allowed)
__device__ u64 g_final[S_][NBP_][H2_][2];
__device__ u64 g_init [S_][NBP_][H2_][2];

// precomputed constants (k_pre)
__device__ float2 g_lam [H2_];     // lambda
__device__ float2 g_lam2[H2_];     // lambda^2
__device__ float2 g_lamL[H2_];     // lambda^L
__device__ float  g_B1[H2_][NU_];  // B[h]   * exp(mB[h])
__device__ float  g_B2[H2_][NU_];  // B[h+H2]* exp(mB[h+H2])
__device__ float  g_C1[H2_][NU_];  // re*B1 - im*B2
__device__ float  g_C2[H2_][NU_];  // im*B1 + re*B2

// ---- packed f32x2 helpers (Blackwell FFMA2 path) ----
static __device__ __forceinline__ u64 pk2(float lo, float hi) {
    u64 r; asm("mov.b64 %0, {%1,%2};" : "=l"(r) : "f"(lo), "f"(hi)); return r;
}
static __device__ __forceinline__ void upk2(u64 v, float& lo, float& hi) {
    asm("mov.b64 {%0,%1}, %2;" : "=f"(lo), "=f"(hi) : "l"(v));
}
static __device__ __forceinline__ u64 ffma2(u64 a, u64 b, u64 c) {
    u64 d; asm("fma.rn.f32x2 %0,%1,%2,%3;" : "=l"(d) : "l"(a), "l"(b), "l"(c)); return d;
}
static __device__ __forceinline__ u64 fmul2(u64 a, u64 b) {
    u64 d; asm("mul.rn.f32x2 %0,%1,%2;" : "=l"(d) : "l"(a), "l"(b)); return d;
}
static __device__ __forceinline__ u64 fadd2(u64 a, u64 b) {
    u64 d; asm("add.rn.f32x2 %0,%1,%2;" : "=l"(d) : "l"(a), "l"(b)); return d;
}
static __device__ __forceinline__ u64 splat(float v) { return pk2(v, v); }

// =====================================================================
// Kernel 0: one-time constant precompute (all DP math lives here)
// <<<1, 128>>>
// =====================================================================
__global__ void k_pre(
    const float* __restrict__ lr, const float* __restrict__ li,
    const float* __restrict__ B, const float* __restrict__ mB)
{
    const int h = threadIdx.x;
    double e1 = exp((double)mB[h]);
    double e2 = exp((double)mB[h + H2_]);
    double r  = exp(-fabs((double)lr[h]));
    double th = 1.5707963267948966 * (double)li[h];
    double re = r * cos(th);
    double im = r * sin(th);
    g_lam[h]  = make_float2((float)re, (float)im);
    g_lam2[h] = make_float2((float)(re * re - im * im), (float)(2.0 * re * im));
    double pr = re, pi = im;
#pragma unroll
    for (int i = 0; i < NSQ_; ++i) {
        double nr = pr * pr - pi * pi;
        double ni = 2.0 * pr * pi;
        pr = nr; pi = ni;
    }
    g_lamL[h] = make_float2((float)pr, (float)pi);
#pragma unroll
    for (int u = 0; u < NU_; ++u) {
        double b1 = (double)B[h * NU_ + u] * e1;
        double b2 = (double)B[(h + H2_) * NU_ + u] * e2;
        g_B1[h][u] = (float)b1;
        g_B2[h][u] = (float)b2;
        g_C1[h][u] = (float)(re * b1 - im * b2);
        g_C2[h][u] = (float)(im * b1 + re * b2);
    }
}

// =====================================================================
// Kernel 1: per-segment local scan (zero init, 2-step fused) -> g_final
// grid (NBP_, S_), 128 threads (one complex pair each, packed over 2 batches)
// =====================================================================
__global__ void __launch_bounds__(128, 4) k_seg(const float* __restrict__ U)
{
    const int h  = threadIdx.x;
    const int bp = blockIdx.x;
    const int s  = blockIdx.y;
    const int b0 = bp << 1;

    u64 B1s[NU_], B2s[NU_], C1s[NU_], C2s[NU_];
#pragma unroll
    for (int u = 0; u < NU_; ++u) {
        B1s[u] = splat(g_B1[h][u]);
        B2s[u] = splat(g_B2[h][u]);
        C1s[u] = splat(g_C1[h][u]);
        C2s[u] = splat(g_C2[h][u]);
    }
    float2 l2 = g_lam2[h];
    u64 R2 = splat(l2.x), I2 = splat(l2.y), nI2 = splat(-l2.y);

    u64 x1 = 0ull, x2 = 0ull;

    __shared__ __align__(16) u64 Us[CH_][NU_];
    const float* Ub = U + ((size_t)s * L_ * NB_ + b0) * NU_;

    for (int c = 0; c < NCH_; ++c) {
        __syncthreads();
        {   // stage CH_ steps of U, packed over the batch pair
            int t = h >> 3, u = h & 7;
            const float* p = Ub + (size_t)(c * CH_ + t) * (NB_ * NU_) + u;
            Us[t][u] = pk2(p[0], p[NU_]);
        }
        __syncthreads();
#pragma unroll
        for (int i = 0; i < CH_ / 2; ++i) {
            // load u_t (A) and u_{t+1} (B)
            const ulonglong2* pa = (const ulonglong2*)(&Us[2 * i][0]);
            ulonglong2 a0 = pa[0], a1 = pa[1], a2 = pa[2], a3 = pa[3];
            const ulonglong2* pb = (const ulonglong2*)(&Us[2 * i + 1][0]);
            ulonglong2 bq0 = pb[0], bq1 = pb[1], bq2 = pb[2], bq3 = pb[3];
            u64 uA[8] = { a0.x, a0.y, a1.x, a1.y, a2.x, a2.y, a3.x, a3.y };
            u64 uB[8] = { bq0.x, bq0.y, bq1.x, bq1.y, bq2.x, bq2.y, bq3.x, bq3.y };

            // acc1 = C1.uA + B1.uB   (two depth-8 chains + combine)
            u64 p1 = fmul2(C1s[0], uA[0]);
            u64 q1 = fmul2(B1s[0], uB[0]);
            u64 p2 = fmul2(C2s[0], uA[0]);
            u64 q2 = fmul2(B2s[0], uB[0]);
#pragma unroll
            for (int u = 1; u < NU_; ++u) {
                p1 = ffma2(C1s[u], uA[u], p1);
                q1 = ffma2(B1s[u], uB[u], q1);
                p2 = ffma2(C2s[u], uA[u], p2);
                q2 = ffma2(B2s[u], uB[u], q2);
            }
            u64 acc1 = fadd2(p1, q1);
            u64 acc2 = fadd2(p2, q2);

            u64 nx1 = ffma2(R2, x1, ffma2(nI2, x2, acc1));
            u64 nx2 = ffma2(I2, x1, ffma2(R2, x2, acc2));
            x1 = nx1; x2 = nx2;
        }
    }
    g_final[s][bp][h][0] = x1;
    g_final[s][bp][h][1] = x2;
}

// =====================================================================
// Kernel 2: sequential combine across segments -> g_init
// grid (NBP_), 128 threads
// =====================================================================
__global__ void __launch_bounds__(128, 1) k_comb(
    const float* __restrict__ y0,
    const float* __restrict__ Wyx, const float* __restrict__ byx)
{
    const int h  = threadIdx.x;
    const int bp = blockIdx.x;
    const int b0 = bp << 1;

    float2 lL = g_lamL[h];
    u64 pr2 = splat(lL.x), pi2 = splat(lL.y), npi2 = splat(-lL.y);

    // x0 = y0 @ Wy2x^T + by2x, packed over batch pair
    u64 z1 = splat(byx[h]), z2 = splat(byx[h + H2_]);
#pragma unroll
    for (int y = 0; y < NY_; ++y) {
        u64 yv = pk2(y0[b0 * NY_ + y], y0[(b0 + 1) * NY_ + y]);
        z1 = ffma2(splat(Wyx[h * NY_ + y]), yv, z1);
        z2 = ffma2(splat(Wyx[(h + H2_) * NY_ + y]), yv, z2);
    }
#pragma unroll
    for (int s = 0; s < S_; ++s) {
        g_init[s][bp][h][0] = z1;
        g_init[s][bp][h][1] = z2;
        u64 f1 = g_final[s][bp][h][0];
        u64 f2 = g_final[s][bp][h][1];
        u64 n1 = ffma2(pr2, z1, ffma2(npi2, z2, f1));
        u64 n2 = ffma2(pr2, z2, ffma2(pi2,  z1, f2));
        z1 = n1; z2 = n2;
    }
}

// =====================================================================
// Kernel 3: re-scan with correct init + fused Y projection
// grid (NBP_, S_), 128 threads, dynamic shared
// shared layout (u64): Xs[CH_][XROW_] | Wk[NH_][NY_] | Us[CH_][NU_] | Rd[4][CH_][NY_]
// =====================================================================
#define SM3_U64 (CH_ * XROW_ + NH_ * NY_ + CH_ * NU_ + 4 * CH_ * NY_)
#define SM3_BYTES (SM3_U64 * 8)

__global__ void __launch_bounds__(128, 4) k_main(
    const float* __restrict__ U,
    const float* __restrict__ Wxy, const float* __restrict__ bxy,
    float* __restrict__ Y)
{
    extern __shared__ __align__(16) u64 sm[];
    u64* Xs = sm;                        // [CH_][XROW_], col k: 2h->x1, 2h+1->x2
    u64* Wk = sm + CH_ * XROW_;          // [NH_][NY_], packed splats, interleaved cols
    u64* Us = Wk + NH_ * NY_;            // [CH_][NU_]
    u64* Rd = Us + CH_ * NU_;            // [4][CH_][NY_] (after in-warp kg-pair reduce)

    const int tid = threadIdx.x;
    const int h   = tid;
    const int bp  = blockIdx.x;
    const int s   = blockIdx.y;
    const int b0  = bp << 1;

    // prepack W (interleave column order to match Xs layout)
#pragma unroll
    for (int i = 0; i < 16; ++i) {
        int idx = tid * 16 + i;          // 0..2047
        int k = idx >> 3, y = idx & 7;
        int hh = k >> 1;
        int col = (k & 1) ? (hh + H2_) : hh;
        float w = Wxy[y * NH_ + col];
        Wk[k * NY_ + y] = pk2(w, w);
    }

    u64 Bp1[NU_], Bp2[NU_];
#pragma unroll
    for (int u = 0; u < NU_; ++u) {
        Bp1[u] = splat(g_B1[h][u]);
        Bp2[u] = splat(g_B2[h][u]);
    }
    float2 lm = g_lam[h];
    u64 re2 = splat(lm.x), im2 = splat(lm.y), ni2 = splat(-lm.y);

    u64 x1 = g_init[s][bp][h][0];
    u64 x2 = g_init[s][bp][h][1];

    // output-role constants
    const int ot = tid >> 3;             // t within chunk for the final reduce
    const int oy = tid & 7;
    const u64 biasp = splat(bxy[oy]);

    // phase-B role
    const int pt = tid & 15;             // t within chunk
    const int kg = tid >> 4;             // 0..7 -> k range [32kg, 32kg+32)
    const int kbase = kg * 32;
    const bool kg_even = ((tid >> 4) & 1) == 0;
    const int g = kg >> 1;               // 0..3 after in-warp pair reduce

    const float* Ub = U + ((size_t)s * L_ * NB_ + b0) * NU_;

    for (int c = 0; c < NCH_; ++c) {
        __syncthreads();
        {   // stage U chunk
            int t = tid >> 3, u = tid & 7;
            const float* p = Ub + (size_t)(c * CH_ + t) * (NB_ * NU_) + u;
            Us[t * NU_ + u] = pk2(p[0], p[NU_]);
        }
        __syncthreads();

        // ---- phase A: scan CH_ steps, stash states in shared ----
#pragma unroll
        for (int t = 0; t < CH_; ++t) {
            const ulonglong2* up = (const ulonglong2*)(Us + t * NU_);
            ulonglong2 ua = up[0], ub = up[1], uc = up[2], ud = up[3];
            u64 uu[8] = { ua.x, ua.y, ub.x, ub.y, uc.x, uc.y, ud.x, ud.y };
            u64 bu1 = fmul2(Bp1[0], uu[0]);
            u64 bu2 = fmul2(Bp2[0], uu[0]);
#pragma unroll
            for (int u = 1; u < NU_; ++u) {
                bu1 = ffma2(Bp1[u], uu[u], bu1);
                bu2 = ffma2(Bp2[u], uu[u], bu2);
            }
            u64 nx1 = ffma2(re2, x1, ffma2(ni2, x2, bu1));
            u64 nx2 = ffma2(re2, x2, ffma2(im2, x1, bu2));
            x1 = nx1; x2 = nx2;
            *((ulonglong2*)(Xs + (size_t)t * XROW_ + 2 * h)) = make_ulonglong2(x1, x2);
        }
        __syncthreads();

        // ---- phase B: Y partial GEMM, thread = (pt, kg), all 8 y ----
        u64 acc[NY_];
#pragma unroll
        for (int y = 0; y < NY_; ++y) acc[y] = 0ull;
        const u64* xrow = Xs + (size_t)pt * XROW_ + kbase;
#pragma unroll
        for (int k4 = 0; k4 < 32; k4 += 4) {
            ulonglong2 xa = *((const ulonglong2*)(xrow + k4));
            ulonglong2 xb = *((const ulonglong2*)(xrow + k4 + 2));
            u64 xv[4] = { xa.x, xa.y, xb.x, xb.y };
#pragma unroll
            for (int j = 0; j < 4; ++j) {
                const ulonglong2* wr = (const ulonglong2*)(Wk + (size_t)(kbase + k4 + j) * NY_);
                ulonglong2 w0 = wr[0], w1 = wr[1], w2 = wr[2], w3 = wr[3];
                acc[0] = ffma2(w0.x, xv[j], acc[0]);
                acc[1] = ffma2(w0.y, xv[j], acc[1]);
                acc[2] = ffma2(w1.x, xv[j], acc[2]);
                acc[3] = ffma2(w1.y, xv[j], acc[3]);
                acc[4] = ffma2(w2.x, xv[j], acc[4]);
                acc[5] = ffma2(w2.y, xv[j], acc[5]);
                acc[6] = ffma2(w3.x, xv[j], acc[6]);
                acc[7] = ffma2(w3.y, xv[j], acc[7]);
            }
        }

        // in-warp pre-reduce: lane tid^16 has same pt, kg^1
#pragma unroll
        for (int y = 0; y < NY_; ++y) {
            u64 o = __shfl_xor_sync(0xFFFFFFFFu, acc[y], 16);
            acc[y] = fadd2(acc[y], o);
        }
        if (kg_even) {
#pragma unroll
            for (int y = 0; y < NY_; y += 2) {
                *((ulonglong2*)(Rd + (size_t)(g * CH_ + pt) * NY_ + y)) =
                    make_ulonglong2(acc[y], acc[y + 1]);
            }
        }
        __syncthreads();

        // ---- final reduce over 4 groups + bias + store ----
        {
            u64 sum = Rd[(size_t)(0 * CH_ + ot) * NY_ + oy];
#pragma unroll
            for (int gg = 1; gg < 4; ++gg)
                sum = fadd2(sum, Rd[(size_t)(gg * CH_ + ot) * NY_ + oy]);
            sum = fadd2(sum, biasp);
            float f0, f1; upk2(sum, f0, f1);
            int tg = s * L_ + c * CH_ + ot;
            float* yp = Y + ((size_t)tg * NB_ + b0) * NY_ + oy;
            yp[0]   = f0;
            yp[NY_] = f1;
        }
    }
}

// =====================================================================
extern "C" void kernel_launch(void* const* d_in, const int* in_sizes, int n_in,
                              void* d_out, int out_size)
{
    const float* y0  = (const float*)d_in[0];
    const float* U   = (const float*)d_in[1];
    const float* lr  = (const float*)d_in[2];
    const float* li  = (const float*)d_in[3];
    const float* B   = (const float*)d_in[4];
    const float* mB  = (const float*)d_in[5];
    const float* Wyx = (const float*)d_in[6];
    const float* byx = (const float*)d_in[7];
    const float* Wxy = (const float*)d_in[8];
    const float* bxy = (const float*)d_in[9];
    float* Y = (float*)d_out;

    cudaFuncSetAttribute(k_main, cudaFuncAttributeMaxDynamicSharedMemorySize, SM3_BYTES);

    dim3 grid(NBP_, S_);
    k_pre <<<1, 128>>>(lr, li, B, mB);
    k_seg <<<grid, 128>>>(U);
    k_comb<<<NBP_, 128>>>(y0, Wyx, byx);
    k_main<<<grid, 128, SM3_BYTES>>>(U, Wxy, bxy, Y);
}

// round 9
// speedup vs baseline: 1.3116x; 1.0012x over previous
#include <cuda_runtime.h>
#include <math.h>

typedef unsigned long long u64;

#define T_    2048
#define NB_   64
#define NU_   8
#define NH_   256
#define H2_   128
#define NY_   8
#define S_    32
#define L_    64           // T_/S_
#define NSQ_  6            // log2(L_)
#define NBP_  32           // NB_/2 (batch pairs)
#define CH_   16           // chunk of timesteps
#define NCH_  4            // L_/CH_
#define XROW_ 258          // padded Xs row (in u64)

// scratch (device globals; no allocation allowed)
__device__ u64 g_final[S_][NBP_][H2_][2];
__device__ u64 g_init [S_][NBP_][H2_][2];

// precomputed constants (k_pre)
__device__ float2 g_lam [H2_];     // lambda
__device__ float2 g_lam2[H2_];     // lambda^2
__device__ float2 g_lamL[H2_];     // lambda^L
__device__ float  g_B1[H2_][NU_];  // B[h]   * exp(mB[h])
__device__ float  g_B2[H2_][NU_];  // B[h+H2]* exp(mB[h+H2])
__device__ float  g_C1[H2_][NU_];  // re*B1 - im*B2
__device__ float  g_C2[H2_][NU_];  // im*B1 + re*B2

// ---- packed f32x2 helpers (Blackwell FFMA2 path) ----
static __device__ __forceinline__ u64 pk2(float lo, float hi) {
    u64 r; asm("mov.b64 %0, {%1,%2};" : "=l"(r) : "f"(lo), "f"(hi)); return r;
}
static __device__ __forceinline__ void upk2(u64 v, float& lo, float& hi) {
    asm("mov.b64 {%0,%1}, %2;" : "=f"(lo), "=f"(hi) : "l"(v));
}
static __device__ __forceinline__ u64 ffma2(u64 a, u64 b, u64 c) {
    u64 d; asm("fma.rn.f32x2 %0,%1,%2,%3;" : "=l"(d) : "l"(a), "l"(b), "l"(c)); return d;
}
static __device__ __forceinline__ u64 fmul2(u64 a, u64 b) {
    u64 d; asm("mul.rn.f32x2 %0,%1,%2;" : "=l"(d) : "l"(a), "l"(b)); return d;
}
static __device__ __forceinline__ u64 fadd2(u64 a, u64 b) {
    u64 d; asm("add.rn.f32x2 %0,%1,%2;" : "=l"(d) : "l"(a), "l"(b)); return d;
}
static __device__ __forceinline__ u64 splat(float v) { return pk2(v, v); }

// =====================================================================
// Kernel 0: one-time constant precompute (all DP math lives here)
// =====================================================================
__global__ void k_pre(
    const float* __restrict__ lr, const float* __restrict__ li,
    const float* __restrict__ B, const float* __restrict__ mB)
{
    const int h = threadIdx.x;
    double e1 = exp((double)mB[h]);
    double e2 = exp((double)mB[h + H2_]);
    double r  = exp(-fabs((double)lr[h]));
    double th = 1.5707963267948966 * (double)li[h];
    double re = r * cos(th);
    double im = r * sin(th);
    g_lam[h]  = make_float2((float)re, (float)im);
    g_lam2[h] = make_float2((float)(re * re - im * im), (float)(2.0 * re * im));
    double pr = re, pi = im;
#pragma unroll
    for (int i = 0; i < NSQ_; ++i) {
        double nr = pr * pr - pi * pi;
        double ni = 2.0 * pr * pi;
        pr = nr; pi = ni;
    }
    g_lamL[h] = make_float2((float)pr, (float)pi);
#pragma unroll
    for (int u = 0; u < NU_; ++u) {
        double b1 = (double)B[h * NU_ + u] * e1;
        double b2 = (double)B[(h + H2_) * NU_ + u] * e2;
        g_B1[h][u] = (float)b1;
        g_B2[h][u] = (float)b2;
        g_C1[h][u] = (float)(re * b1 - im * b2);
        g_C2[h][u] = (float)(im * b1 + re * b2);
    }
}

// =====================================================================
// Kernel 1: per-segment local scan (zero init, 2-step fused) -> g_final
// =====================================================================
__global__ void __launch_bounds__(128, 4) k_seg(const float* __restrict__ U)
{
    const int h  = threadIdx.x;
    const int bp = blockIdx.x;
    const int s  = blockIdx.y;
    const int b0 = bp << 1;

    u64 B1s[NU_], B2s[NU_], C1s[NU_], C2s[NU_];
#pragma unroll
    for (int u = 0; u < NU_; ++u) {
        B1s[u] = splat(g_B1[h][u]);
        B2s[u] = splat(g_B2[h][u]);
        C1s[u] = splat(g_C1[h][u]);
        C2s[u] = splat(g_C2[h][u]);
    }
    float2 l2 = g_lam2[h];
    u64 R2 = splat(l2.x), I2 = splat(l2.y), nI2 = splat(-l2.y);

    u64 x1 = 0ull, x2 = 0ull;

    __shared__ __align__(16) u64 Us[CH_][NU_];
    const float* Ub = U + ((size_t)s * L_ * NB_ + b0) * NU_;

    for (int c = 0; c < NCH_; ++c) {
        __syncthreads();
        {
            int t = h >> 3, u = h & 7;
            const float* p = Ub + (size_t)(c * CH_ + t) * (NB_ * NU_) + u;
            Us[t][u] = pk2(p[0], p[NU_]);
        }
        __syncthreads();
#pragma unroll
        for (int i = 0; i < CH_ / 2; ++i) {
            const ulonglong2* pa = (const ulonglong2*)(&Us[2 * i][0]);
            ulonglong2 a0 = pa[0], a1 = pa[1], a2 = pa[2], a3 = pa[3];
            const ulonglong2* pb = (const ulonglong2*)(&Us[2 * i + 1][0]);
            ulonglong2 bq0 = pb[0], bq1 = pb[1], bq2 = pb[2], bq3 = pb[3];
            u64 uA[8] = { a0.x, a0.y, a1.x, a1.y, a2.x, a2.y, a3.x, a3.y };
            u64 uB[8] = { bq0.x, bq0.y, bq1.x, bq1.y, bq2.x, bq2.y, bq3.x, bq3.y };

            u64 p1 = fmul2(C1s[0], uA[0]);
            u64 q1 = fmul2(B1s[0], uB[0]);
            u64 p2 = fmul2(C2s[0], uA[0]);
            u64 q2 = fmul2(B2s[0], uB[0]);
#pragma unroll
            for (int u = 1; u < NU_; ++u) {
                p1 = ffma2(C1s[u], uA[u], p1);
                q1 = ffma2(B1s[u], uB[u], q1);
                p2 = ffma2(C2s[u], uA[u], p2);
                q2 = ffma2(B2s[u], uB[u], q2);
            }
            u64 acc1 = fadd2(p1, q1);
            u64 acc2 = fadd2(p2, q2);

            u64 nx1 = ffma2(R2, x1, ffma2(nI2, x2, acc1));
            u64 nx2 = ffma2(I2, x1, ffma2(R2, x2, acc2));
            x1 = nx1; x2 = nx2;
        }
    }
    g_final[s][bp][h][0] = x1;
    g_final[s][bp][h][1] = x2;
}

// =====================================================================
// Kernel 2: sequential combine across segments -> g_init
// =====================================================================
__global__ void __launch_bounds__(128, 1) k_comb(
    const float* __restrict__ y0,
    const float* __restrict__ Wyx, const float* __restrict__ byx)
{
    const int h  = threadIdx.x;
    const int bp = blockIdx.x;
    const int b0 = bp << 1;

    float2 lL = g_lamL[h];
    u64 pr2 = splat(lL.x), pi2 = splat(lL.y), npi2 = splat(-lL.y);

    u64 z1 = splat(byx[h]), z2 = splat(byx[h + H2_]);
#pragma unroll
    for (int y = 0; y < NY_; ++y) {
        u64 yv = pk2(y0[b0 * NY_ + y], y0[(b0 + 1) * NY_ + y]);
        z1 = ffma2(splat(Wyx[h * NY_ + y]), yv, z1);
        z2 = ffma2(splat(Wyx[(h + H2_) * NY_ + y]), yv, z2);
    }
#pragma unroll
    for (int s = 0; s < S_; ++s) {
        g_init[s][bp][h][0] = z1;
        g_init[s][bp][h][1] = z2;
        u64 f1 = g_final[s][bp][h][0];
        u64 f2 = g_final[s][bp][h][1];
        u64 n1 = ffma2(pr2, z1, ffma2(npi2, z2, f1));
        u64 n2 = ffma2(pr2, z2, ffma2(pi2,  z1, f2));
        z1 = n1; z2 = n2;
    }
}

// =====================================================================
// Kernel 3: re-scan with correct init + fused Y projection
// grid (NBP_, S_), 128 threads, dynamic shared
// shared (u64): Xs[CH_][XROW_] | WkT[NY_][NH_] | Us[CH_][NU_]
// Phase B: thread = (warp tg -> 4 timesteps) x (lane kg -> k strided by 32)
//          warp butterfly allreduce -> direct store to Y (no Rd)
// =====================================================================
#define SM3_U64 (CH_ * XROW_ + NY_ * NH_ + CH_ * NU_)
#define SM3_BYTES (SM3_U64 * 8)

__global__ void __launch_bounds__(128, 4) k_main(
    const float* __restrict__ U,
    const float* __restrict__ Wxy, const float* __restrict__ bxy,
    float* __restrict__ Y)
{
    extern __shared__ __align__(16) u64 sm[];
    u64* Xs  = sm;                        // [CH_][XROW_], col k: 2h->x1, 2h+1->x2
    u64* WkT = sm + CH_ * XROW_;          // [NY_][NH_] transposed, interleaved cols
    u64* Us  = WkT + NY_ * NH_;           // [CH_][NU_]

    const int tid = threadIdx.x;
    const int h   = tid;
    const int bp  = blockIdx.x;
    const int s   = blockIdx.y;
    const int b0  = bp << 1;

    // prepack W transposed: WkT[y][k] = splat(Wxy[y][colmap(k)])
#pragma unroll
    for (int i = 0; i < 16; ++i) {
        int idx = tid * 16 + i;          // 0..2047
        int y = idx >> 8, k = idx & 255;
        int hh = k >> 1;
        int col = (k & 1) ? (hh + H2_) : hh;
        WkT[y * NH_ + k] = splat(Wxy[y * NH_ + col]);
    }

    u64 Bp1[NU_], Bp2[NU_];
#pragma unroll
    for (int u = 0; u < NU_; ++u) {
        Bp1[u] = splat(g_B1[h][u]);
        Bp2[u] = splat(g_B2[h][u]);
    }
    float2 lm = g_lam[h];
    u64 re2 = splat(lm.x), im2 = splat(lm.y), ni2 = splat(-lm.y);

    u64 x1 = g_init[s][bp][h][0];
    u64 x2 = g_init[s][bp][h][1];

    // phase-B roles
    const int lane = tid & 31;           // kg
    const int tg   = tid >> 5;           // warp -> 4 timesteps
    const int t_local = lane >> 3;       // output role after allreduce
    const int oy      = lane & 7;
    const u64 biasp = splat(bxy[oy]);

    const float* Ub = U + ((size_t)s * L_ * NB_ + b0) * NU_;

    for (int c = 0; c < NCH_; ++c) {
        __syncthreads();                 // Xs reads (prev chunk) done before rewrite
        {
            int t = tid >> 3, u = tid & 7;
            const float* p = Ub + (size_t)(c * CH_ + t) * (NB_ * NU_) + u;
            Us[t * NU_ + u] = pk2(p[0], p[NU_]);
        }
        __syncthreads();

        // ---- phase A: scan CH_ steps, stash states in shared ----
#pragma unroll
        for (int t = 0; t < CH_; ++t) {
            const ulonglong2* up = (const ulonglong2*)(Us + t * NU_);
            ulonglong2 ua = up[0], ub = up[1], uc = up[2], ud = up[3];
            u64 uu[8] = { ua.x, ua.y, ub.x, ub.y, uc.x, uc.y, ud.x, ud.y };
            u64 bu1 = fmul2(Bp1[0], uu[0]);
            u64 bu2 = fmul2(Bp2[0], uu[0]);
#pragma unroll
            for (int u = 1; u < NU_; ++u) {
                bu1 = ffma2(Bp1[u], uu[u], bu1);
                bu2 = ffma2(Bp2[u], uu[u], bu2);
            }
            u64 nx1 = ffma2(re2, x1, ffma2(ni2, x2, bu1));
            u64 nx2 = ffma2(re2, x2, ffma2(im2, x1, bu2));
            x1 = nx1; x2 = nx2;
            *((ulonglong2*)(Xs + (size_t)t * XROW_ + 2 * h)) = make_ulonglong2(x1, x2);
        }
        __syncthreads();

        // ---- phase B: Y GEMM, thread = (tg: 4 t) x (lane: k strided by 32) ----
        u64 acc[32];
#pragma unroll
        for (int v = 0; v < 32; ++v) acc[v] = 0ull;

        const u64* xb0 = Xs + (size_t)(tg * 4 + 0) * XROW_ + lane;
        const u64* xb1 = Xs + (size_t)(tg * 4 + 1) * XROW_ + lane;
        const u64* xb2 = Xs + (size_t)(tg * 4 + 2) * XROW_ + lane;
        const u64* xb3 = Xs + (size_t)(tg * 4 + 3) * XROW_ + lane;
        const u64* wb  = WkT + lane;

#pragma unroll
        for (int j = 0; j < 8; ++j) {
            const int ko = j * 32;
            u64 xv0 = xb0[ko], xv1 = xb1[ko], xv2 = xb2[ko], xv3 = xb3[ko];
            u64 w0 = wb[0 * NH_ + ko], w1 = wb[1 * NH_ + ko];
            u64 w2 = wb[2 * NH_ + ko], w3 = wb[3 * NH_ + ko];
            u64 w4 = wb[4 * NH_ + ko], w5 = wb[5 * NH_ + ko];
            u64 w6 = wb[6 * NH_ + ko], w7 = wb[7 * NH_ + ko];

            acc[ 0] = ffma2(w0, xv0, acc[ 0]); acc[ 1] = ffma2(w1, xv0, acc[ 1]);
            acc[ 2] = ffma2(w2, xv0, acc[ 2]); acc[ 3] = ffma2(w3, xv0, acc[ 3]);
            acc[ 4] = ffma2(w4, xv0, acc[ 4]); acc[ 5] = ffma2(w5, xv0, acc[ 5]);
            acc[ 6] = ffma2(w6, xv0, acc[ 6]); acc[ 7] = ffma2(w7, xv0, acc[ 7]);
            acc[ 8] = ffma2(w0, xv1, acc[ 8]); acc[ 9] = ffma2(w1, xv1, acc[ 9]);
            acc[10] = ffma2(w2, xv1, acc[10]); acc[11] = ffma2(w3, xv1, acc[11]);
            acc[12] = ffma2(w4, xv1, acc[12]); acc[13] = ffma2(w5, xv1, acc[13]);
            acc[14] = ffma2(w6, xv1, acc[14]); acc[15] = ffma2(w7, xv1, acc[15]);
            acc[16] = ffma2(w0, xv2, acc[16]); acc[17] = ffma2(w1, xv2, acc[17]);
            acc[18] = ffma2(w2, xv2, acc[18]); acc[19] = ffma2(w3, xv2, acc[19]);
            acc[20] = ffma2(w4, xv2, acc[20]); acc[21] = ffma2(w5, xv2, acc[21]);
            acc[22] = ffma2(w6, xv2, acc[22]); acc[23] = ffma2(w7, xv2, acc[23]);
            acc[24] = ffma2(w0, xv3, acc[24]); acc[25] = ffma2(w1, xv3, acc[25]);
            acc[26] = ffma2(w2, xv3, acc[26]); acc[27] = ffma2(w3, xv3, acc[27]);
            acc[28] = ffma2(w4, xv3, acc[28]); acc[29] = ffma2(w5, xv3, acc[29]);
            acc[30] = ffma2(w6, xv3, acc[30]); acc[31] = ffma2(w7, xv3, acc[31]);
        }

        // ---- butterfly allreduce over 32 lanes with value exchange ----
        // after step d, each lane keeps half its set; final: lane owns v = lane
        {
            int n = 32;
#pragma unroll
            for (int d = 16; d >= 1; d >>= 1) {
                n >>= 1;
                const bool hi = (lane & d) != 0;
#pragma unroll
                for (int i = 0; i < 16; ++i) {
                    if (i < n) {
                        u64 snd = hi ? acc[i] : acc[i + n];
                        u64 rcv = __shfl_xor_sync(0xFFFFFFFFu, snd, d);
                        u64 kp  = hi ? acc[i + n] : acc[i];
                        acc[i] = fadd2(kp, rcv);
                    }
                }
            }
        }

        // lane owns (t_local, oy) fully reduced; add bias, store straight to Y
        {
            u64 r = fadd2(acc[0], biasp);
            float f0, f1; upk2(r, f0, f1);
            int tgl = s * L_ + c * CH_ + tg * 4 + t_local;
            float* yp = Y + ((size_t)tgl * NB_ + b0) * NY_ + oy;
            yp[0]   = f0;
            yp[NY_] = f1;
        }
    }
}

// =====================================================================
extern "C" void kernel_launch(void* const* d_in, const int* in_sizes, int n_in,
                              void* d_out, int out_size)
{
    const float* y0  = (const float*)d_in[0];
    const float* U   = (const float*)d_in[1];
    const float* lr  = (const float*)d_in[2];
    const float* li  = (const float*)d_in[3];
    const float* B   = (const float*)d_in[4];
    const float* mB  = (const float*)d_in[5];
    const float* Wyx = (const float*)d_in[6];
    const float* byx = (const float*)d_in[7];
    const float* Wxy = (const float*)d_in[8];
    const float* bxy = (const float*)d_in[9];
    float* Y = (float*)d_out;

    cudaFuncSetAttribute(k_main, cudaFuncAttributeMaxDynamicSharedMemorySize, SM3_BYTES);

    dim3 grid(NBP_, S_);
    k_pre <<<1, 128>>>(lr, li, B, mB);
    k_seg <<<grid, 128>>>(U);
    k_comb<<<NBP_, 128>>>(y0, Wyx, byx);
    k_main<<<grid, 128, SM3_BYTES>>>(U, Wxy, bxy, Y);
}